// round 1
// baseline (speedup 1.0000x reference)
#include <cuda_runtime.h>

// HJB loss: mean over B rows of
//   s = 2*(xr0*dyn0 + xr1*dyn1) + xr2*dyn2 + xr3*dyn3 + V + 0.05*(u0^2+u1^2) + 0.25*sigma^2
// with xr = X - (1,0,0,0),
//      V   = xr0^2 + xr1^2 + 0.5*xr2^2 + 0.5*xr3^2
//      dyn0 = X2 + 0.3*u0
//      dyn1 = X3 + 0.25*u1
//      dyn2 = 0.6*X1 + u0 + 0.5*mu0
//      dyn3 = -0.6*X0 + u1 + 0.5*mu1
// (Q, R, x_target, f, G, COV are the fixed constants from setup_inputs/reference;
//  trace(2Q @ COV COV^T) = 0.5 -> trace_term = 0.25*sigma^2.)

#define RBLOCKS 2048
#define RTHREADS 256

__device__ float g_partials[RBLOCKS];

__global__ __launch_bounds__(RTHREADS)
void hjb_pass1(const float4* __restrict__ X,
               const float2* __restrict__ mu,
               const float*  __restrict__ sigma,
               const float2* __restrict__ u,
               int B)
{
    const int tid    = blockIdx.x * blockDim.x + threadIdx.x;
    const int stride = gridDim.x * blockDim.x;

    float acc = 0.0f;

    for (int i = tid; i < B; i += stride) {
        float4 x  = X[i];
        float2 m  = mu[i];
        float2 uu = u[i];
        float  sg = sigma[i];

        float xr0 = x.x - 1.0f;
        float xr1 = x.y;
        float xr2 = x.z;
        float xr3 = x.w;

        float dyn0 = fmaf(0.3f,  uu.x, x.z);
        float dyn1 = fmaf(0.25f, uu.y, x.w);
        float dyn2 = fmaf(0.6f,  x.y, uu.x) + 0.5f * m.x;
        float dyn3 = fmaf(-0.6f, x.x, uu.y) + 0.5f * m.y;

        float g = 2.0f * (xr0 * dyn0 + xr1 * dyn1) + xr2 * dyn2 + xr3 * dyn3;

        float V = xr0 * xr0 + xr1 * xr1 + 0.5f * (xr2 * xr2 + xr3 * xr3);

        float uRu = 0.05f * (uu.x * uu.x + uu.y * uu.y);
        float tr  = 0.25f * sg * sg;

        acc += g + V + uRu + tr;
    }

    // warp reduce
    #pragma unroll
    for (int off = 16; off > 0; off >>= 1)
        acc += __shfl_xor_sync(0xFFFFFFFFu, acc, off);

    __shared__ float s_warp[RTHREADS / 32];
    int lane = threadIdx.x & 31;
    int wid  = threadIdx.x >> 5;
    if (lane == 0) s_warp[wid] = acc;
    __syncthreads();

    if (wid == 0) {
        float v = (lane < (RTHREADS / 32)) ? s_warp[lane] : 0.0f;
        #pragma unroll
        for (int off = 4; off > 0; off >>= 1)
            v += __shfl_xor_sync(0xFFFFFFFFu, v, off);
        if (lane == 0) g_partials[blockIdx.x] = v;
    }
}

__global__ __launch_bounds__(1024)
void hjb_pass2(float* __restrict__ out, int B)
{
    // 2048 partials, 1024 threads -> 2 each; accumulate in double for the
    // final combine, then divide by B.
    int t = threadIdx.x;
    double v = (double)g_partials[t] + (double)g_partials[t + 1024];

    // block reduce in shared (double)
    __shared__ double s[1024];
    s[t] = v;
    __syncthreads();
    for (int off = 512; off > 0; off >>= 1) {
        if (t < off) s[t] += s[t + off];
        __syncthreads();
    }
    if (t == 0) out[0] = (float)(s[0] / (double)B);
}

extern "C" void kernel_launch(void* const* d_in, const int* in_sizes, int n_in,
                              void* d_out, int out_size)
{
    const float4* X     = (const float4*)d_in[0];
    const float2* mu    = (const float2*)d_in[1];
    const float*  sigma = (const float*) d_in[2];
    const float2* u     = (const float2*)d_in[3];
    float* out = (float*)d_out;

    int B = in_sizes[2];  // sigma has B elements

    hjb_pass1<<<RBLOCKS, RTHREADS>>>(X, mu, sigma, u, B);
    hjb_pass2<<<1, 1024>>>(out, B);
}